// round 3
// baseline (speedup 1.0000x reference)
#include <cuda_runtime.h>

#define BB 4
#define C 256
#define H 64
#define W 64
#define HW 4096
#define G 32
#define KK 9
#define OC_OFF 18
#define CK 2304  /* C * KK */

// ---------------- device scratch (static, no runtime allocation) -------------
__device__ float g_offset[BB * OC_OFF * HW];            // 1.18 MB
__device__ float g_val[(size_t)BB * CK * HW];           // 151 MB
__device__ float g_tmp[(size_t)BB * C * HW];            // 16.8 MB (pre-GN GEMM out)
__device__ float g_act[(size_t)BB * C * HW];            // 16.8 MB (stage-1 activated)

// ---------------- init offset buffer with bias -------------------------------
__global__ void init_offset_kernel(const float* __restrict__ bias) {
    int i = blockIdx.x * 256 + threadIdx.x;
    if (i < BB * OC_OFF * HW) {
        int oc = (i / HW) % OC_OFF;
        g_offset[i] = bias[oc];
    }
}

// ---------------- offset conv3x3: C in -> 18 out, pad 1 ----------------------
// grid (4,4, B*4): z = b*4 + cin_chunk (chunks of 64). block 256 = 16x16 pixels
#define CIN_CHUNK 64
__global__ __launch_bounds__(256) void offset_conv_kernel(
    const float* __restrict__ xin, const float* __restrict__ woff, int use_internal) {
    __shared__ __align__(16) float ws[CIN_CHUNK * 9 * 20];  // [cl][k][oc pad 20]
    __shared__ float xs[18 * 18];

    int tid = threadIdx.x;
    int bz = blockIdx.z;
    int b = bz >> 2;
    int chunk = bz & 3;
    int cin0 = chunk * CIN_CHUNK;

    // load weight chunk: woff[oc][cin][k] -> ws[cl][k][oc]
    for (int idx = tid; idx < CIN_CHUNK * 9 * 18; idx += 256) {
        int cl = idx / 162;
        int rem = idx - cl * 162;
        int k = rem / 18;
        int oc = rem - k * 18;
        ws[(cl * 9 + k) * 20 + oc] =
            woff[(size_t)oc * (C * 9) + (size_t)(cin0 + cl) * 9 + k];
    }

    int ty = tid >> 4, tx = tid & 15;
    int py0 = blockIdx.y * 16, px0 = blockIdx.x * 16;

    float acc[18];
#pragma unroll
    for (int i = 0; i < 18; i++) acc[i] = 0.f;

    const float* src = use_internal ? g_act : xin;
    const float* xb = src + ((size_t)b * C + cin0) * HW;

    __syncthreads();

    for (int cl = 0; cl < CIN_CHUNK; cl++) {
        const float* xc = xb + (size_t)cl * HW;
        // load 18x18 halo tile (zero padded)
        for (int idx = tid; idx < 324; idx += 256) {
            int r = idx / 18, cc = idx - r * 18;
            int gy = py0 - 1 + r, gx = px0 - 1 + cc;
            float v = 0.f;
            if (gy >= 0 && gy < H && gx >= 0 && gx < W) v = xc[gy * W + gx];
            xs[idx] = v;
        }
        __syncthreads();

        float xv[9];
#pragma unroll
        for (int ky = 0; ky < 3; ky++)
#pragma unroll
            for (int kx = 0; kx < 3; kx++)
                xv[ky * 3 + kx] = xs[(ty + ky) * 18 + (tx + kx)];

#pragma unroll
        for (int k = 0; k < 9; k++) {
            const float* wr = &ws[(cl * 9 + k) * 20];
            float xk = xv[k];
#pragma unroll
            for (int oc = 0; oc < 18; oc++) acc[oc] += xk * wr[oc];
        }
        __syncthreads();
    }

    int p = (py0 + ty) * W + (px0 + tx);
    float* ob = g_offset + (size_t)b * OC_OFF * HW + p;
#pragma unroll
    for (int oc = 0; oc < 18; oc++) atomicAdd(ob + (size_t)oc * HW, acc[oc]);
}

// ---------------- bilinear gather -> val[b][cin*9+k][p] ----------------------
// grid (16, 9, B), block 256 (one thread per pixel; loops cin)
__global__ __launch_bounds__(256) void gather_kernel(const float* __restrict__ xin,
                                                     int use_internal) {
    int tid = threadIdx.x;
    int p = blockIdx.x * 256 + tid;
    int k = blockIdx.y;
    int b = blockIdx.z;
    int h = p >> 6, w = p & 63;

    const float* off = g_offset + ((size_t)b * OC_OFF + 2 * k) * HW + p;
    float dy = off[0];
    float dx = off[HW];
    int ky = k / 3, kx = k - ky * 3;

    float py = dy + (float)(h - 1 + ky);
    float px = dx + (float)(w - 1 + kx);
    float fy = floorf(py), fx = floorf(px);
    int iy0 = (int)fy, ix0 = (int)fx;
    float ly = py - fy, lx = px - fx;

    float vy0 = (iy0 >= 0 && iy0 < H) ? 1.f : 0.f;
    float vy1 = (iy0 + 1 >= 0 && iy0 + 1 < H) ? 1.f : 0.f;
    float vx0 = (ix0 >= 0 && ix0 < W) ? 1.f : 0.f;
    float vx1 = (ix0 + 1 >= 0 && ix0 + 1 < W) ? 1.f : 0.f;

    float w00 = (1.f - ly) * (1.f - lx) * vy0 * vx0;
    float w01 = (1.f - ly) * lx * vy0 * vx1;
    float w10 = ly * (1.f - lx) * vy1 * vx0;
    float w11 = ly * lx * vy1 * vx1;

    int cy0 = min(max(iy0, 0), H - 1);
    int cy1 = min(max(iy0 + 1, 0), H - 1);
    int cx0 = min(max(ix0, 0), W - 1);
    int cx1 = min(max(ix0 + 1, 0), W - 1);
    int i00 = cy0 * W + cx0, i01 = cy0 * W + cx1;
    int i10 = cy1 * W + cx0, i11 = cy1 * W + cx1;

    const float* src = use_internal ? g_act : xin;
    const float* xb = src + (size_t)b * C * HW;
    float* vo = g_val + ((size_t)b * CK + k) * HW + p;

#pragma unroll 4
    for (int cin = 0; cin < C; cin++) {
        const float* xc = xb + (size_t)cin * HW;
        float s = w00 * __ldg(xc + i00) + w01 * __ldg(xc + i01) +
                  w10 * __ldg(xc + i10) + w11 * __ldg(xc + i11);
        vo[(size_t)cin * 9 * HW] = s;
    }
}

// ---------------- SGEMM: out[b][m][p] = sum_r Wt[m][r] * val[b][r][p] --------
// 128x128 tile, BK=8, 256 threads, 8x8 microtile, double-buffered smem.
// grid (32, 2, B)
__global__ __launch_bounds__(256, 2) void gemm_kernel(const float* __restrict__ Wt) {
    __shared__ __align__(16) float As[2][8][132];
    __shared__ __align__(16) float Bs[2][8][128];

    int tid = threadIdx.x;
    int b = blockIdx.z;
    int m0 = blockIdx.y * 128;
    int n0 = blockIdx.x * 128;

    const float* A = Wt + (size_t)m0 * CK;
    const float* Bv = g_val + (size_t)b * CK * HW + n0;
    float* Cp = g_tmp + ((size_t)b * C + m0) * HW + n0;

    int aRow = tid >> 1;        // 0..127
    int aCol = (tid & 1) * 4;   // 0 or 4
    int bRow = tid >> 5;        // 0..7
    int bCol = (tid & 31) * 4;  // 0..124
    int ty = tid >> 4, tx = tid & 15;

    float acc[8][8];
#pragma unroll
    for (int i = 0; i < 8; i++)
#pragma unroll
        for (int j = 0; j < 8; j++) acc[i][j] = 0.f;

    // preload tile 0
    float4 a4 = *reinterpret_cast<const float4*>(A + (size_t)aRow * CK + aCol);
    float4 b4 = *reinterpret_cast<const float4*>(Bv + (size_t)bRow * HW + bCol);
    As[0][aCol + 0][aRow] = a4.x;
    As[0][aCol + 1][aRow] = a4.y;
    As[0][aCol + 2][aRow] = a4.z;
    As[0][aCol + 3][aRow] = a4.w;
    *reinterpret_cast<float4*>(&Bs[0][bRow][bCol]) = b4;
    __syncthreads();

    const int NK = CK / 8;  // 288
    int buf = 0;
    for (int kb = 0; kb < NK; kb++) {
        float4 an, bn;
        if (kb + 1 < NK) {
            an = *reinterpret_cast<const float4*>(A + (size_t)aRow * CK +
                                                  (size_t)(kb + 1) * 8 + aCol);
            bn = *reinterpret_cast<const float4*>(
                Bv + ((size_t)(kb + 1) * 8 + bRow) * HW + bCol);
        }
#pragma unroll
        for (int kk = 0; kk < 8; kk++) {
            float4 af0 = *reinterpret_cast<const float4*>(&As[buf][kk][ty * 8]);
            float4 af1 = *reinterpret_cast<const float4*>(&As[buf][kk][ty * 8 + 4]);
            float4 bf0 = *reinterpret_cast<const float4*>(&Bs[buf][kk][tx * 8]);
            float4 bf1 = *reinterpret_cast<const float4*>(&Bs[buf][kk][tx * 8 + 4]);
            float a[8] = {af0.x, af0.y, af0.z, af0.w, af1.x, af1.y, af1.z, af1.w};
            float bbv[8] = {bf0.x, bf0.y, bf0.z, bf0.w, bf1.x, bf1.y, bf1.z, bf1.w};
#pragma unroll
            for (int i = 0; i < 8; i++)
#pragma unroll
                for (int j = 0; j < 8; j++) acc[i][j] += a[i] * bbv[j];
        }
        if (kb + 1 < NK) {
            int nb = buf ^ 1;
            As[nb][aCol + 0][aRow] = an.x;
            As[nb][aCol + 1][aRow] = an.y;
            As[nb][aCol + 2][aRow] = an.z;
            As[nb][aCol + 3][aRow] = an.w;
            *reinterpret_cast<float4*>(&Bs[nb][bRow][bCol]) = bn;
            __syncthreads();
            buf = nb;
        }
    }

#pragma unroll
    for (int i = 0; i < 8; i++) {
        float4 o0 = {acc[i][0], acc[i][1], acc[i][2], acc[i][3]};
        float4 o1 = {acc[i][4], acc[i][5], acc[i][6], acc[i][7]};
        float* row = Cp + (size_t)(ty * 8 + i) * HW + tx * 8;
        *reinterpret_cast<float4*>(row) = o0;
        *reinterpret_cast<float4*>(row + 4) = o1;
    }
}

// ---------------- GroupNorm (+ReLU, optional residual) -----------------------
// grid = B*G blocks, 256 threads. reads g_tmp; writes g_act (internal) or outp.
__global__ __launch_bounds__(256) void gn_kernel(const float* __restrict__ gamma,
                                                 const float* __restrict__ beta,
                                                 const float* __restrict__ residual,
                                                 float* __restrict__ outp,
                                                 int use_internal) {
    int b = blockIdx.x >> 5;
    int g = blockIdx.x & 31;
    size_t chan_off = ((size_t)b * C + (size_t)g * 8) * HW;
    const float* base = g_tmp + chan_off;

    int tid = threadIdx.x;
    float s = 0.f, ss = 0.f;
    const float4* in4 = reinterpret_cast<const float4*>(base);
    for (int i = tid; i < 8 * HW / 4; i += 256) {
        float4 v = in4[i];
        s += v.x + v.y + v.z + v.w;
        ss += v.x * v.x + v.y * v.y + v.z * v.z + v.w * v.w;
    }
#pragma unroll
    for (int o = 16; o > 0; o >>= 1) {
        s += __shfl_xor_sync(0xffffffffu, s, o);
        ss += __shfl_xor_sync(0xffffffffu, ss, o);
    }
    __shared__ float red[8], red2[8], stats[2];
    int wid = tid >> 5, lid = tid & 31;
    if (lid == 0) { red[wid] = s; red2[wid] = ss; }
    __syncthreads();
    if (tid == 0) {
        float ts = 0.f, tss = 0.f;
#pragma unroll
        for (int i = 0; i < 8; i++) { ts += red[i]; tss += red2[i]; }
        float inv_n = 1.f / 32768.f;
        float mu = ts * inv_n;
        stats[0] = mu;
        stats[1] = rsqrtf(tss * inv_n - mu * mu + 1e-5f);
    }
    __syncthreads();
    float mu = stats[0], rstd = stats[1];

    float* dst = (use_internal ? g_act : outp) + chan_off;
    float4* out4 = reinterpret_cast<float4*>(dst);
    const float4* res4 =
        residual ? reinterpret_cast<const float4*>(residual + chan_off) : nullptr;

    for (int i = tid; i < 8 * HW / 4; i += 256) {
        int c = g * 8 + (i >> 10);  // i*4/4096
        float gm = gamma[c] * rstd;
        float bt = beta[c] - mu * gm;
        float4 v = in4[i];
        v.x = v.x * gm + bt;
        v.y = v.y * gm + bt;
        v.z = v.z * gm + bt;
        v.w = v.w * gm + bt;
        if (res4) {
            float4 r = res4[i];
            v.x += r.x; v.y += r.y; v.z += r.z; v.w += r.w;
        }
        v.x = fmaxf(v.x, 0.f);
        v.y = fmaxf(v.y, 0.f);
        v.z = fmaxf(v.z, 0.f);
        v.w = fmaxf(v.w, 0.f);
        out4[i] = v;
    }
}

// ---------------- launcher ---------------------------------------------------
extern "C" void kernel_launch(void* const* d_in, const int* in_sizes, int n_in,
                              void* d_out, int out_size) {
    const float* x      = (const float*)d_in[0];
    const float* w_off1 = (const float*)d_in[1];
    const float* b_off1 = (const float*)d_in[2];
    const float* w_off2 = (const float*)d_in[3];
    const float* b_off2 = (const float*)d_in[4];
    const float* w_def1 = (const float*)d_in[5];
    const float* w_def2 = (const float*)d_in[6];
    const float* gamma1 = (const float*)d_in[7];
    const float* beta1  = (const float*)d_in[8];
    const float* gamma2 = (const float*)d_in[9];
    const float* beta2  = (const float*)d_in[10];
    float* out = (float*)d_out;

    dim3 conv_grid(4, 4, BB * 4);
    dim3 gath_grid(HW / 256, KK, BB);
    dim3 gemm_grid(HW / 128, C / 128, BB);
    int init_blocks = (BB * OC_OFF * HW + 255) / 256;

    // ---- stage 1 ----
    init_offset_kernel<<<init_blocks, 256>>>(b_off1);
    offset_conv_kernel<<<conv_grid, 256>>>(x, w_off1, 0);
    gather_kernel<<<gath_grid, 256>>>(x, 0);
    gemm_kernel<<<gemm_grid, 256>>>(w_def1);
    gn_kernel<<<BB * G, 256>>>(gamma1, beta1, nullptr, nullptr, 1);

    // ---- stage 2 ----
    init_offset_kernel<<<init_blocks, 256>>>(b_off2);
    offset_conv_kernel<<<conv_grid, 256>>>(nullptr, w_off2, 1);
    gather_kernel<<<gath_grid, 256>>>(nullptr, 1);
    gemm_kernel<<<gemm_grid, 256>>>(w_def2);
    gn_kernel<<<BB * G, 256>>>(gamma2, beta2, x, out, 0);
}

// round 6
// speedup vs baseline: 1.3033x; 1.3033x over previous
#include <cuda_runtime.h>
#include <cuda_bf16.h>
#include <cstdint>

#define BB 4
#define C 256
#define H 64
#define W 64
#define HW 4096
#define G 32
#define KK 9
#define OC_OFF 18
#define CK 2304  /* C * KK */

// ---------------- device scratch (static, no runtime allocation) -------------
__device__ float g_offset[BB * OC_OFF * HW];                             // 1.18 MB
__device__ __align__(16) unsigned short g_val_hi[(size_t)BB * HW * CK];  // 75.5 MB
__device__ __align__(16) unsigned short g_val_lo[(size_t)BB * HW * CK];  // 75.5 MB
__device__ __align__(16) unsigned short g_whi[2 * C * CK];               // 2.36 MB
__device__ __align__(16) unsigned short g_wlo[2 * C * CK];               // 2.36 MB
__device__ float g_tmp[(size_t)BB * C * HW];                             // 16.8 MB
__device__ float g_act[(size_t)BB * C * HW];                             // 16.8 MB

// ---------------- helpers ----------------------------------------------------
__device__ __forceinline__ uint32_t smem_u32(const void* p) {
    uint32_t a;
    asm("{ .reg .u64 t; cvta.to.shared.u64 t, %1; cvt.u32.u64 %0, t; }"
        : "=r"(a) : "l"(p));
    return a;
}
__device__ __forceinline__ void cp16(uint32_t saddr, const void* gaddr) {
    asm volatile("cp.async.cg.shared.global [%0], [%1], 16;"
                 :: "r"(saddr), "l"(gaddr));
}

#define MMA_BF16(d, a, bfr)                                                  \
    asm volatile(                                                            \
        "mma.sync.aligned.m16n8k16.row.col.f32.bf16.bf16.f32 "               \
        "{%0,%1,%2,%3}, {%4,%5,%6,%7}, {%8,%9}, {%0,%1,%2,%3};"              \
        : "+f"((d)[0]), "+f"((d)[1]), "+f"((d)[2]), "+f"((d)[3])             \
        : "r"((a)[0]), "r"((a)[1]), "r"((a)[2]), "r"((a)[3]),                \
          "r"((bfr)[0]), "r"((bfr)[1]))

#define LDSM_X4(fr, addr)                                                    \
    asm volatile("ldmatrix.sync.aligned.m8n8.x4.shared.b16 "                 \
                 "{%0,%1,%2,%3}, [%4];"                                      \
                 : "=r"((fr)[0]), "=r"((fr)[1]), "=r"((fr)[2]), "=r"((fr)[3])\
                 : "r"(addr))

#define LDSM_X2(fr, addr)                                                    \
    asm volatile("ldmatrix.sync.aligned.m8n8.x2.shared.b16 {%0,%1}, [%2];"   \
                 : "=r"((fr)[0]), "=r"((fr)[1]) : "r"(addr))

// ---------------- init offset buffer with bias -------------------------------
__global__ void init_offset_kernel(const float* __restrict__ bias) {
    int i = blockIdx.x * 256 + threadIdx.x;
    if (i < BB * OC_OFF * HW) {
        int oc = (i / HW) % OC_OFF;
        g_offset[i] = bias[oc];
    }
}

// ---------------- weight split/reorder: w[oc][cin][k] -> [oc][k*256+cin] -----
__global__ void wprep_kernel(const float* __restrict__ w1, const float* __restrict__ w2) {
    int i = blockIdx.x * 256 + threadIdx.x;
    if (i >= 2 * C * CK) return;
    int s = i / (C * CK);
    int rem = i - s * (C * CK);
    int oc = rem / CK;
    int r = rem - oc * CK;
    int k = r >> 8;
    int cin = r & 255;
    const float* w = s ? w2 : w1;
    float v = w[(size_t)oc * CK + cin * 9 + k];
    __nv_bfloat16 h = __float2bfloat16(v);
    g_whi[i] = __bfloat16_as_ushort(h);
    g_wlo[i] = __bfloat16_as_ushort(__float2bfloat16(v - __bfloat162float(h)));
}

// ---------------- offset conv3x3: C in -> 18 out, pad 1 ----------------------
#define CIN_CHUNK 64
__global__ __launch_bounds__(256) void offset_conv_kernel(
    const float* __restrict__ xin, const float* __restrict__ woff, int use_internal) {
    __shared__ __align__(16) float ws[CIN_CHUNK * 9 * 20];
    __shared__ float xs[18 * 18];

    int tid = threadIdx.x;
    int bz = blockIdx.z;
    int b = bz >> 2;
    int chunk = bz & 3;
    int cin0 = chunk * CIN_CHUNK;

    for (int idx = tid; idx < CIN_CHUNK * 9 * 18; idx += 256) {
        int cl = idx / 162;
        int rem = idx - cl * 162;
        int k = rem / 18;
        int oc = rem - k * 18;
        ws[(cl * 9 + k) * 20 + oc] =
            woff[(size_t)oc * (C * 9) + (size_t)(cin0 + cl) * 9 + k];
    }

    int ty = tid >> 4, tx = tid & 15;
    int py0 = blockIdx.y * 16, px0 = blockIdx.x * 16;

    float acc[18];
#pragma unroll
    for (int i = 0; i < 18; i++) acc[i] = 0.f;

    const float* src = use_internal ? g_act : xin;
    const float* xb = src + ((size_t)b * C + cin0) * HW;

    __syncthreads();

    for (int cl = 0; cl < CIN_CHUNK; cl++) {
        const float* xc = xb + (size_t)cl * HW;
        for (int idx = tid; idx < 324; idx += 256) {
            int r = idx / 18, cc = idx - r * 18;
            int gy = py0 - 1 + r, gx = px0 - 1 + cc;
            float v = 0.f;
            if (gy >= 0 && gy < H && gx >= 0 && gx < W) v = xc[gy * W + gx];
            xs[idx] = v;
        }
        __syncthreads();

        float xv[9];
#pragma unroll
        for (int ky = 0; ky < 3; ky++)
#pragma unroll
            for (int kx = 0; kx < 3; kx++)
                xv[ky * 3 + kx] = xs[(ty + ky) * 18 + (tx + kx)];

#pragma unroll
        for (int k = 0; k < 9; k++) {
            const float* wr = &ws[(cl * 9 + k) * 20];
            float xk = xv[k];
#pragma unroll
            for (int oc = 0; oc < 18; oc++) acc[oc] += xk * wr[oc];
        }
        __syncthreads();
    }

    int p = (py0 + ty) * W + (px0 + tx);
    float* ob = g_offset + (size_t)b * OC_OFF * HW + p;
#pragma unroll
    for (int oc = 0; oc < 18; oc++) atomicAdd(ob + (size_t)oc * HW, acc[oc]);
}

// ---------------- bilinear gather -> val_{hi,lo}[b][p][k*256+cin] ------------
__global__ __launch_bounds__(256) void gather_kernel(const float* __restrict__ xin,
                                                     int use_internal) {
    int tid = threadIdx.x;
    int p = blockIdx.x * 256 + tid;
    int k = blockIdx.y;
    int b = blockIdx.z;
    int h = p >> 6, w = p & 63;

    const float* off = g_offset + ((size_t)b * OC_OFF + 2 * k) * HW + p;
    float dy = off[0];
    float dx = off[HW];
    int ky = k / 3, kx = k - ky * 3;

    float py = dy + (float)(h - 1 + ky);
    float px = dx + (float)(w - 1 + kx);
    float fy = floorf(py), fx = floorf(px);
    int iy0 = (int)fy, ix0 = (int)fx;
    float ly = py - fy, lx = px - fx;

    float vy0 = (iy0 >= 0 && iy0 < H) ? 1.f : 0.f;
    float vy1 = (iy0 + 1 >= 0 && iy0 + 1 < H) ? 1.f : 0.f;
    float vx0 = (ix0 >= 0 && ix0 < W) ? 1.f : 0.f;
    float vx1 = (ix0 + 1 >= 0 && ix0 + 1 < W) ? 1.f : 0.f;

    float w00 = (1.f - ly) * (1.f - lx) * vy0 * vx0;
    float w01 = (1.f - ly) * lx * vy0 * vx1;
    float w10 = ly * (1.f - lx) * vy1 * vx0;
    float w11 = ly * lx * vy1 * vx1;

    int cy0 = min(max(iy0, 0), H - 1);
    int cy1 = min(max(iy0 + 1, 0), H - 1);
    int cx0 = min(max(ix0, 0), W - 1);
    int cx1 = min(max(ix0 + 1, 0), W - 1);
    int i00 = cy0 * W + cx0, i01 = cy0 * W + cx1;
    int i10 = cy1 * W + cx0, i11 = cy1 * W + cx1;

    const float* src = use_internal ? g_act : xin;
    const float* xb = src + (size_t)b * C * HW;
    size_t vbase = ((size_t)b * HW + p) * CK + (size_t)k * 256;
    unsigned short* vh = g_val_hi + vbase;
    unsigned short* vl = g_val_lo + vbase;

    for (int c0 = 0; c0 < C; c0 += 8) {
        __align__(16) unsigned short hb[8];
        __align__(16) unsigned short lb[8];
#pragma unroll
        for (int j = 0; j < 8; j++) {
            const float* xc = xb + (size_t)(c0 + j) * HW;
            float s = w00 * __ldg(xc + i00) + w01 * __ldg(xc + i01) +
                      w10 * __ldg(xc + i10) + w11 * __ldg(xc + i11);
            __nv_bfloat16 hv = __float2bfloat16(s);
            hb[j] = __bfloat16_as_ushort(hv);
            lb[j] = __bfloat16_as_ushort(__float2bfloat16(s - __bfloat162float(hv)));
        }
        *reinterpret_cast<uint4*>(vh + c0) = *reinterpret_cast<const uint4*>(hb);
        *reinterpret_cast<uint4*>(vl + c0) = *reinterpret_cast<const uint4*>(lb);
    }
}

// ---------------- HMMA GEMM: D[p, oc] = sum_r val[p][r] * W[oc][r] -----------
// CTA tile 128(pixels) x 128(oc), KC=32 double-buffered cp.async.
// bf16x3 split: AhBh + AlBh + AhBl, fp32 accum. 8 warps, 64x32 warp tiles.
// Rows padded to 80B (stride 5 x 16B, coprime with 8 -> conflict-free ldmatrix).
#define KC 32
#define NKC (CK / KC) /* 72 */
#define ROWB 80
#define A_HI 0
#define A_LO (128 * ROWB)
#define B_HI (2 * 128 * ROWB)
#define B_LO (3 * 128 * ROWB)
#define BUFSZ (4 * 128 * ROWB) /* 40960 */
#define GSMEM (2 * BUFSZ)      /* 81920 */

__global__ __launch_bounds__(256, 2) void mma_gemm_kernel(int stage) {
    extern __shared__ __align__(16) char smem[];
    uint32_t sb = smem_u32(smem);
    int tid = threadIdx.x;
    int wid = tid >> 5, lane = tid & 31;
    int b = blockIdx.z;
    int n0 = blockIdx.y * 128;
    int p0 = blockIdx.x * 128;

    const unsigned short* Ah = g_val_hi + ((size_t)b * HW + p0) * CK;
    const unsigned short* Al = g_val_lo + ((size_t)b * HW + p0) * CK;
    const unsigned short* Bh = g_whi + ((size_t)stage * C + n0) * CK;
    const unsigned short* Bl = g_wlo + ((size_t)stage * C + n0) * CK;

    // load assignment: thread -> row tid>>1 (both A pixel-row and B oc-row),
    // half (tid&1) covers bytes [0,32) or [32,64) of the 64B row chunk.
    int lrow = tid >> 1;
    int lseg = (tid & 1) * 2;
    size_t goff = (size_t)lrow * CK + lseg * 8;
    uint32_t soff = (uint32_t)lrow * ROWB + (uint32_t)lseg * 16;

    int mwarp = wid >> 2, nwarp = wid & 3;
    uint32_t aoff = (uint32_t)(mwarp * 64 + (lane & 15)) * ROWB + (lane >> 4) * 16;
    uint32_t boff = (uint32_t)(nwarp * 32 + (lane & 7)) * ROWB + ((lane >> 3) & 1) * 16;

    float acc[4][4][4];
#pragma unroll
    for (int i = 0; i < 4; i++)
#pragma unroll
        for (int j = 0; j < 4; j++)
#pragma unroll
            for (int q = 0; q < 4; q++) acc[i][j][q] = 0.f;

    // prologue: buffer 0 <- kc 0
    {
        uint32_t bufb = sb;
        cp16(bufb + A_HI + soff, Ah + goff);
        cp16(bufb + A_HI + soff + 16, Ah + goff + 8);
        cp16(bufb + A_LO + soff, Al + goff);
        cp16(bufb + A_LO + soff + 16, Al + goff + 8);
        cp16(bufb + B_HI + soff, Bh + goff);
        cp16(bufb + B_HI + soff + 16, Bh + goff + 8);
        cp16(bufb + B_LO + soff, Bl + goff);
        cp16(bufb + B_LO + soff + 16, Bl + goff + 8);
        asm volatile("cp.async.commit_group;" ::: "memory");
    }

#pragma unroll 1
    for (int i = 0; i < NKC; i++) {
        if (i + 1 < NKC) {
            uint32_t bufb = sb + (uint32_t)((i + 1) & 1) * BUFSZ;
            int kc = (i + 1) * KC;
            cp16(bufb + A_HI + soff, Ah + goff + kc);
            cp16(bufb + A_HI + soff + 16, Ah + goff + kc + 8);
            cp16(bufb + A_LO + soff, Al + goff + kc);
            cp16(bufb + A_LO + soff + 16, Al + goff + kc + 8);
            cp16(bufb + B_HI + soff, Bh + goff + kc);
            cp16(bufb + B_HI + soff + 16, Bh + goff + kc + 8);
            cp16(bufb + B_LO + soff, Bl + goff + kc);
            cp16(bufb + B_LO + soff + 16, Bl + goff + kc + 8);
            asm volatile("cp.async.commit_group;" ::: "memory");
            asm volatile("cp.async.wait_group 1;" ::: "memory");
        } else {
            asm volatile("cp.async.wait_group 0;" ::: "memory");
        }
        __syncthreads();

        uint32_t cb = sb + (uint32_t)(i & 1) * BUFSZ;
#pragma unroll
        for (int kk = 0; kk < 2; kk++) {
            uint32_t koff = (uint32_t)kk * 32;
            uint32_t ah[4][4], bhf[4][2];
#pragma unroll
            for (int nt = 0; nt < 4; nt++)
                LDSM_X2(bhf[nt], cb + B_HI + boff + (uint32_t)(nt * 8) * ROWB + koff);
#pragma unroll
            for (int mt = 0; mt < 4; mt++)
                LDSM_X4(ah[mt], cb + A_HI + aoff + (uint32_t)(mt * 16) * ROWB + koff);
#pragma unroll
            for (int mt = 0; mt < 4; mt++)
#pragma unroll
                for (int nt = 0; nt < 4; nt++) MMA_BF16(acc[mt][nt], ah[mt], bhf[nt]);
            // A_lo x B_hi
#pragma unroll
            for (int mt = 0; mt < 4; mt++) {
                uint32_t alf[4];
                LDSM_X4(alf, cb + A_LO + aoff + (uint32_t)(mt * 16) * ROWB + koff);
#pragma unroll
                for (int nt = 0; nt < 4; nt++) MMA_BF16(acc[mt][nt], alf, bhf[nt]);
            }
            // A_hi x B_lo
#pragma unroll
            for (int nt = 0; nt < 4; nt++) {
                uint32_t blf[2];
                LDSM_X2(blf, cb + B_LO + boff + (uint32_t)(nt * 8) * ROWB + koff);
#pragma unroll
                for (int mt = 0; mt < 4; mt++) MMA_BF16(acc[mt][nt], ah[mt], blf);
            }
        }
        __syncthreads();
    }

    // ---------------- epilogue: smem transpose [n][m] then coalesced stores --
    float* sf = reinterpret_cast<float*>(smem);
    int rl = lane >> 2;
    int cl2 = (lane & 3) * 2;
#pragma unroll
    for (int mt = 0; mt < 4; mt++) {
#pragma unroll
        for (int nt = 0; nt < 4; nt++) {
            int m = mwarp * 64 + mt * 16 + rl;
            int n = nwarp * 32 + nt * 8 + cl2;
            sf[n * 132 + m] = acc[mt][nt][0];
            sf[(n + 1) * 132 + m] = acc[mt][nt][1];
            sf[n * 132 + m + 8] = acc[mt][nt][2];
            sf[(n + 1) * 132 + m + 8] = acc[mt][nt][3];
        }
    }
    __syncthreads();

    float* Cp = g_tmp + ((size_t)b * C + n0) * HW + p0;
#pragma unroll
    for (int t = 0; t < 16; t++) {
        int idx = tid + t * 256;
        int n = idx >> 5;
        int ms = (idx & 31) * 4;
        float4 v = *reinterpret_cast<const float4*>(sf + n * 132 + ms);
        *reinterpret_cast<float4*>(Cp + (size_t)n * HW + ms) = v;
    }
}

// ---------------- GroupNorm (+ReLU, optional residual) -----------------------
__global__ __launch_bounds__(256) void gn_kernel(const float* __restrict__ gamma,
                                                 const float* __restrict__ beta,
                                                 const float* __restrict__ residual,
                                                 float* __restrict__ outp,
                                                 int use_internal) {
    int b = blockIdx.x >> 5;
    int g = blockIdx.x & 31;
    size_t chan_off = ((size_t)b * C + (size_t)g * 8) * HW;
    const float* base = g_tmp + chan_off;

    int tid = threadIdx.x;
    float s = 0.f, ss = 0.f;
    const float4* in4 = reinterpret_cast<const float4*>(base);
    for (int i = tid; i < 8 * HW / 4; i += 256) {
        float4 v = in4[i];
        s += v.x + v.y + v.z + v.w;
        ss += v.x * v.x + v.y * v.y + v.z * v.z + v.w * v.w;
    }
#pragma unroll
    for (int o = 16; o > 0; o >>= 1) {
        s += __shfl_xor_sync(0xffffffffu, s, o);
        ss += __shfl_xor_sync(0xffffffffu, ss, o);
    }
    __shared__ float red[8], red2[8], stats[2];
    int wid = tid >> 5, lid = tid & 31;
    if (lid == 0) { red[wid] = s; red2[wid] = ss; }
    __syncthreads();
    if (tid == 0) {
        float ts = 0.f, tss = 0.f;
#pragma unroll
        for (int i = 0; i < 8; i++) { ts += red[i]; tss += red2[i]; }
        float inv_n = 1.f / 32768.f;
        float mu = ts * inv_n;
        stats[0] = mu;
        stats[1] = rsqrtf(tss * inv_n - mu * mu + 1e-5f);
    }
    __syncthreads();
    float mu = stats[0], rstd = stats[1];

    float* dst = (use_internal ? g_act : outp) + chan_off;
    float4* out4 = reinterpret_cast<float4*>(dst);
    const float4* res4 =
        residual ? reinterpret_cast<const float4*>(residual + chan_off) : nullptr;

    for (int i = tid; i < 8 * HW / 4; i += 256) {
        int c = g * 8 + (i >> 10);
        float gm = gamma[c] * rstd;
        float bt = beta[c] - mu * gm;
        float4 v = in4[i];
        v.x = v.x * gm + bt;
        v.y = v.y * gm + bt;
        v.z = v.z * gm + bt;
        v.w = v.w * gm + bt;
        if (res4) {
            float4 r = res4[i];
            v.x += r.x; v.y += r.y; v.z += r.z; v.w += r.w;
        }
        v.x = fmaxf(v.x, 0.f);
        v.y = fmaxf(v.y, 0.f);
        v.z = fmaxf(v.z, 0.f);
        v.w = fmaxf(v.w, 0.f);
        out4[i] = v;
    }
}

// ---------------- launcher ---------------------------------------------------
extern "C" void kernel_launch(void* const* d_in, const int* in_sizes, int n_in,
                              void* d_out, int out_size) {
    const float* x      = (const float*)d_in[0];
    const float* w_off1 = (const float*)d_in[1];
    const float* b_off1 = (const float*)d_in[2];
    const float* w_off2 = (const float*)d_in[3];
    const float* b_off2 = (const float*)d_in[4];
    const float* w_def1 = (const float*)d_in[5];
    const float* w_def2 = (const float*)d_in[6];
    const float* gamma1 = (const float*)d_in[7];
    const float* beta1  = (const float*)d_in[8];
    const float* gamma2 = (const float*)d_in[9];
    const float* beta2  = (const float*)d_in[10];
    float* out = (float*)d_out;

    cudaFuncSetAttribute(mma_gemm_kernel, cudaFuncAttributeMaxDynamicSharedMemorySize,
                         GSMEM);

    dim3 conv_grid(4, 4, BB * 4);
    dim3 gath_grid(HW / 256, KK, BB);
    dim3 gemm_grid(HW / 128, C / 128, BB);
    int init_blocks = (BB * OC_OFF * HW + 255) / 256;
    int wprep_blocks = (2 * C * CK + 255) / 256;

    wprep_kernel<<<wprep_blocks, 256>>>(w_def1, w_def2);

    // ---- stage 1 ----
    init_offset_kernel<<<init_blocks, 256>>>(b_off1);
    offset_conv_kernel<<<conv_grid, 256>>>(x, w_off1, 0);
    gather_kernel<<<gath_grid, 256>>>(x, 0);
    mma_gemm_kernel<<<gemm_grid, 256, GSMEM>>>(0);
    gn_kernel<<<BB * G, 256>>>(gamma1, beta1, nullptr, nullptr, 1);

    // ---- stage 2 ----
    init_offset_kernel<<<init_blocks, 256>>>(b_off2);
    offset_conv_kernel<<<conv_grid, 256>>>(nullptr, w_off2, 1);
    gather_kernel<<<gath_grid, 256>>>(nullptr, 1);
    mma_gemm_kernel<<<gemm_grid, 256, GSMEM>>>(1);
    gn_kernel<<<BB * G, 256>>>(gamma2, beta2, x, out, 0);
}